// round 12
// baseline (speedup 1.0000x reference)
#include <cuda_runtime.h>

// out[b] = -(inp[b,:] . quad)^2 + inp[b,:] . linw + bias
// B = 16384, D = 4096, fp32. 256 MiB streaming read.
//
// Converged finding (R1-R11): LDG / cp.async / TMA all pin at 6.0-6.3 TB/s —
// the achievable streaming-read ceiling on this part (spec 8 TB/s is not
// reachable). Schedule scan: 1 wave = 47.2us, 1.73 waves = 45.06us (best),
// 3.46 waves = 46.4us -> grid 1024 / 16 rows per block is optimal.
//
// R12 = R5 (best: 45.06us) with the row loop unroll widened 2 -> 4 so ptxas
// can front-hoist the next rows' LDG.128 batches across a 4-row window
// (rows are fully independent; loop body is only 4 LDG + 32 FMA + 1 STS).

#ifndef D_DIM
#define D_DIM 4096
#endif

constexpr int THREADS        = 256;            // 8 warps
constexpr int WARPS          = THREADS / 32;   // 8
constexpr int F4_PER_LANE    = (D_DIM / WARPS) / 4 / 32;  // 4
constexpr int ROWS_PER_BLOCK = 16;

__global__ __launch_bounds__(THREADS)
void skinny_quad_kernel(const float* __restrict__ inp,
                        const float* __restrict__ quad,
                        const float* __restrict__ linw,
                        const float* __restrict__ linb,
                        float* __restrict__ out,
                        int B)
{
    // per-lane partials: [row][256 lanes] (float2 = sq, sl) -> 32KB
    __shared__ float2 s_part[ROWS_PER_BLOCK][THREADS];

    const int tid  = threadIdx.x;
    const int lane = tid & 31;
    const int warp = tid >> 5;

    // warp's column chunk: 128 float4 (512 floats)
    const int cbase = warp * (D_DIM / WARPS / 4);

    // Weights in registers, loaded once per block
    const float4* __restrict__ gq = reinterpret_cast<const float4*>(quad) + cbase;
    const float4* __restrict__ gl = reinterpret_cast<const float4*>(linw) + cbase;
    float4 q[F4_PER_LANE], l[F4_PER_LANE];
    #pragma unroll
    for (int i = 0; i < F4_PER_LANE; ++i) {
        q[i] = gq[i * 32 + lane];
        l[i] = gl[i * 32 + lane];
    }
    const float bias = *linb;

    const int row0 = blockIdx.x * ROWS_PER_BLOCK;

    #pragma unroll 4
    for (int r = 0; r < ROWS_PER_BLOCK; ++r) {
        const float4* __restrict__ xr =
            reinterpret_cast<const float4*>(inp + (size_t)(row0 + r) * D_DIM) + cbase;

        float4 x[F4_PER_LANE];
        #pragma unroll
        for (int i = 0; i < F4_PER_LANE; ++i)
            x[i] = xr[i * 32 + lane];

        float sq = 0.f, sl = 0.f;
        #pragma unroll
        for (int i = 0; i < F4_PER_LANE; ++i) {
            sq = fmaf(x[i].x, q[i].x, sq);
            sq = fmaf(x[i].y, q[i].y, sq);
            sq = fmaf(x[i].z, q[i].z, sq);
            sq = fmaf(x[i].w, q[i].w, sq);
            sl = fmaf(x[i].x, l[i].x, sl);
            sl = fmaf(x[i].y, l[i].y, sl);
            sl = fmaf(x[i].z, l[i].z, sl);
            sl = fmaf(x[i].w, l[i].w, sl);
        }

        // fire-and-forget per-lane partial; no shuffles in the stream loop
        s_part[r][tid] = make_float2(sq, sl);
    }

    __syncthreads();

    // Block-wide reduction: 16 threads per row, each sums 16 partials,
    // then a 4-stage shuffle reduce within the 16-thread subgroup.
    {
        const int row = tid >> 4;        // 0..15
        const int sub = tid & 15;        // 0..15

        float sq = 0.f, sl = 0.f;
        #pragma unroll
        for (int k = 0; k < THREADS / 16; ++k) {
            const float2 p = s_part[row][sub + k * 16];
            sq += p.x;
            sl += p.y;
        }

        #pragma unroll
        for (int off = 8; off > 0; off >>= 1) {
            sq += __shfl_down_sync(0xFFFFFFFFu, sq, off, 16);
            sl += __shfl_down_sync(0xFFFFFFFFu, sl, off, 16);
        }

        if (sub == 0) {
            const int orow = row0 + row;
            if (orow < B)
                out[orow] = fmaf(-sq, sq, sl + bias);
        }
    }
}

extern "C" void kernel_launch(void* const* d_in, const int* in_sizes, int n_in,
                              void* d_out, int out_size)
{
    const float* inp  = (const float*)d_in[0];   // (B, D)
    const float* quad = (const float*)d_in[1];   // (D, 1)
    const float* linw = (const float*)d_in[2];   // (1, D)
    const float* linb = (const float*)d_in[3];   // (1,)
    float* out = (float*)d_out;

    const int B = in_sizes[0] / D_DIM;
    const int grid = (B + ROWS_PER_BLOCK - 1) / ROWS_PER_BLOCK;

    skinny_quad_kernel<<<grid, THREADS>>>(inp, quad, linw, linb, out, B);
}

// round 13
// speedup vs baseline: 1.1810x; 1.1810x over previous
#include <cuda_runtime.h>

// out[b] = -(inp[b,:] . quad)^2 + inp[b,:] . linw + bias
// B = 16384, D = 4096, fp32. 256 MiB streaming read.
//
// FINAL (R13 = R5, the measured optimum at 45.06us, DRAM 75.3%):
// 12-round convergence evidence:
//  - LDG / cp.async / TMA all pin at 6.0-6.3 TB/s: the path-independent
//    LTS/HBM streaming ceiling on this part (~78% of 8 TB/s spec).
//  - Schedule scan: 1 wave=47.2us, 1.73 waves=45.06us (best), 3.46=46.4us.
//  - Register boundary is sharp: 64 regs = 4 blocks/SM is the warpsxMLP
//    peak; unroll 4 (68 regs, 3 blocks/SM) -> 53us; forced 80 regs -> 45.5.
//  - Deferred per-lane reduction keeps the stream loop at exactly
//    4 LDG.128 + 32 FMA + 1 STS.64 (fire-and-forget), nothing else.
// Achievable floor ~= 268MB / 6.25TB/s ~= 43us; this runs at ~95% of it.

#ifndef D_DIM
#define D_DIM 4096
#endif

constexpr int THREADS        = 256;            // 8 warps
constexpr int WARPS          = THREADS / 32;   // 8
constexpr int F4_PER_LANE    = (D_DIM / WARPS) / 4 / 32;  // 4
constexpr int ROWS_PER_BLOCK = 16;

__global__ __launch_bounds__(THREADS)
void skinny_quad_kernel(const float* __restrict__ inp,
                        const float* __restrict__ quad,
                        const float* __restrict__ linw,
                        const float* __restrict__ linb,
                        float* __restrict__ out,
                        int B)
{
    // per-lane partials: [row][256 lanes] (float2 = sq, sl) -> 32KB
    __shared__ float2 s_part[ROWS_PER_BLOCK][THREADS];

    const int tid  = threadIdx.x;
    const int lane = tid & 31;
    const int warp = tid >> 5;

    // warp's column chunk: 128 float4 (512 floats)
    const int cbase = warp * (D_DIM / WARPS / 4);

    // Weights in registers, loaded once per block
    const float4* __restrict__ gq = reinterpret_cast<const float4*>(quad) + cbase;
    const float4* __restrict__ gl = reinterpret_cast<const float4*>(linw) + cbase;
    float4 q[F4_PER_LANE], l[F4_PER_LANE];
    #pragma unroll
    for (int i = 0; i < F4_PER_LANE; ++i) {
        q[i] = gq[i * 32 + lane];
        l[i] = gl[i * 32 + lane];
    }

    const int row0 = blockIdx.x * ROWS_PER_BLOCK;

    #pragma unroll 2
    for (int r = 0; r < ROWS_PER_BLOCK; ++r) {
        const float4* __restrict__ xr =
            reinterpret_cast<const float4*>(inp + (size_t)(row0 + r) * D_DIM) + cbase;

        float4 x[F4_PER_LANE];
        #pragma unroll
        for (int i = 0; i < F4_PER_LANE; ++i)
            x[i] = xr[i * 32 + lane];

        float sq = 0.f, sl = 0.f;
        #pragma unroll
        for (int i = 0; i < F4_PER_LANE; ++i) {
            sq = fmaf(x[i].x, q[i].x, sq);
            sq = fmaf(x[i].y, q[i].y, sq);
            sq = fmaf(x[i].z, q[i].z, sq);
            sq = fmaf(x[i].w, q[i].w, sq);
            sl = fmaf(x[i].x, l[i].x, sl);
            sl = fmaf(x[i].y, l[i].y, sl);
            sl = fmaf(x[i].z, l[i].z, sl);
            sl = fmaf(x[i].w, l[i].w, sl);
        }

        // fire-and-forget per-lane partial; no shuffles in the stream loop
        s_part[r][tid] = make_float2(sq, sl);
    }

    __syncthreads();

    // Block-wide reduction: 16 threads per row, each sums 16 partials,
    // then a 4-stage shuffle reduce within the 16-thread subgroup.
    {
        const int row = tid >> 4;        // 0..15
        const int sub = tid & 15;        // 0..15

        float sq = 0.f, sl = 0.f;
        #pragma unroll
        for (int k = 0; k < THREADS / 16; ++k) {
            const float2 p = s_part[row][sub + k * 16];
            sq += p.x;
            sl += p.y;
        }

        #pragma unroll
        for (int off = 8; off > 0; off >>= 1) {
            sq += __shfl_down_sync(0xFFFFFFFFu, sq, off, 16);
            sl += __shfl_down_sync(0xFFFFFFFFu, sl, off, 16);
        }

        if (sub == 0) {
            const int orow = row0 + row;
            if (orow < B) {
                const float bias = *linb;
                out[orow] = fmaf(-sq, sq, sl + bias);
            }
        }
    }
}

extern "C" void kernel_launch(void* const* d_in, const int* in_sizes, int n_in,
                              void* d_out, int out_size)
{
    const float* inp  = (const float*)d_in[0];   // (B, D)
    const float* quad = (const float*)d_in[1];   // (D, 1)
    const float* linw = (const float*)d_in[2];   // (1, D)
    const float* linb = (const float*)d_in[3];   // (1,)
    float* out = (float*)d_out;

    const int B = in_sizes[0] / D_DIM;
    const int grid = (B + ROWS_PER_BLOCK - 1) / ROWS_PER_BLOCK;

    skinny_quad_kernel<<<grid, THREADS>>>(inp, quad, linw, linb, out, B);
}